// round 3
// baseline (speedup 1.0000x reference)
#include <cuda_runtime.h>
#include <cuda_bf16.h>

#define N_NODES 100000
#define N_EDGES 3200000
#define D_FEAT  512
#define HIDDEN  16
#define N_CLS   40

// ---------------- scratch (static device globals; no allocation) -------------
__device__ int    d_is64;
__device__ int    d_src [N_EDGES];
__device__ int    d_dst [N_EDGES];
__device__ int    d_deg [N_NODES];
__device__ float  d_dinv[N_NODES];
__device__ float4 d_g1  [N_NODES * 4];   // dinv[v] * (x[v] @ W1)      (16 f)
__device__ float4 d_acc1[N_NODES * 4];   // self-init + edge scatter   (16 f)
__device__ float4 d_g2  [N_NODES * 4];   // dinv[v] * relu(...)        (16 f)
__device__ float4 d_acc2[N_NODES * 4];   // self-init + edge scatter   (16 f)

__device__ __forceinline__ float4 f4fma(float a, float4 b, float4 c) {
    c.x = fmaf(a, b.x, c.x); c.y = fmaf(a, b.y, c.y);
    c.z = fmaf(a, b.z, c.z); c.w = fmaf(a, b.w, c.w);
    return c;
}
__device__ __forceinline__ float4 f4scale(float a, float4 b) {
    return make_float4(a * b.x, a * b.y, a * b.z, a * b.w);
}

// ---------------- 0) edge dtype detect ---------------------------------------
__global__ void k_detect(const void* __restrict__ ei) {
    if (threadIdx.x == 0 && blockIdx.x == 0) {
        const unsigned long long* p = (const unsigned long long*)ei;
        int is64 = 1;
        for (int i = 0; i < 64; i++)
            if (p[i] >= (unsigned long long)N_NODES) { is64 = 0; break; }
        d_is64 = is64;
    }
}

// ---------------- 1a) zero degrees -------------------------------------------
__global__ void k_init_deg() {
    int i = blockIdx.x * blockDim.x + threadIdx.x;
    if (i < N_NODES) d_deg[i] = 0;
}

// ---------------- 1b) decode edges + count degrees ---------------------------
__global__ void __launch_bounds__(256) k_decode(const void* __restrict__ ei) {
    int i = blockIdx.x * blockDim.x + threadIdx.x;
    if (i >= N_EDGES) return;
    int s, d;
    if (d_is64) {
        const long long* p = (const long long*)ei;
        s = (int)p[i];
        d = (int)p[i + N_EDGES];
    } else {
        const int* p = (const int*)ei;
        s = p[i];
        d = p[i + N_EDGES];
    }
    d_src[i] = s;
    d_dst[i] = d;
    if ((unsigned)d < N_NODES) atomicAdd(&d_deg[d], 1);
}

// ---------------- 1c) dinv = rsqrt(deg + self-loop) --------------------------
__global__ void k_dinv() {
    int i = blockIdx.x * blockDim.x + threadIdx.x;
    if (i < N_NODES) d_dinv[i] = rsqrtf((float)(d_deg[i] + 1));
}

// ---------------- 2) GEMM1: g1 = dinv * (x @ W1); acc1 = g1 ------------------
__global__ void __launch_bounds__(256) k_gemm1(const float* __restrict__ x,
                                               const float* __restrict__ W1) {
    __shared__ float4 Ws[D_FEAT * 4];              // [k][c4], 32 KB
    const float4* wv = (const float4*)W1;
    for (int i = threadIdx.x; i < D_FEAT * 4; i += 256) Ws[i] = wv[i];
    __syncthreads();

    int r = blockIdx.x * 256 + threadIdx.x;
    if (r >= N_NODES) return;

    float4 acc0 = make_float4(0.f, 0.f, 0.f, 0.f);
    float4 acc1 = acc0, acc2 = acc0, acc3 = acc0;
    const float4* xr = (const float4*)(x + (size_t)r * D_FEAT);

#pragma unroll 4
    for (int k4 = 0; k4 < D_FEAT / 4; k4++) {
        float4 xv = xr[k4];
        const float4* w = &Ws[(k4 * 4) * 4];
#pragma unroll
        for (int m = 0; m < 4; m++) {
            float xk = (m == 0) ? xv.x : (m == 1) ? xv.y : (m == 2) ? xv.z : xv.w;
            acc0 = f4fma(xk, w[m * 4 + 0], acc0);
            acc1 = f4fma(xk, w[m * 4 + 1], acc1);
            acc2 = f4fma(xk, w[m * 4 + 2], acc2);
            acc3 = f4fma(xk, w[m * 4 + 3], acc3);
        }
    }
    float dv = d_dinv[r];
    acc0 = f4scale(dv, acc0); acc1 = f4scale(dv, acc1);
    acc2 = f4scale(dv, acc2); acc3 = f4scale(dv, acc3);
    d_g1[r * 4 + 0] = acc0; d_g1[r * 4 + 1] = acc1;
    d_g1[r * 4 + 2] = acc2; d_g1[r * 4 + 3] = acc3;
    d_acc1[r * 4 + 0] = acc0; d_acc1[r * 4 + 1] = acc1;
    d_acc1[r * 4 + 2] = acc2; d_acc1[r * 4 + 3] = acc3;
}

// ---------------- 3) edge scatter: acc[dst] += g[src] (16 floats) ------------
__global__ void __launch_bounds__(256) k_scatter(const float4* __restrict__ g,
                                                 float4* __restrict__ acc) {
    int i = blockIdx.x * blockDim.x + threadIdx.x;
    if (i >= N_EDGES) return;
    unsigned s = (unsigned)d_src[i];
    unsigned d = (unsigned)d_dst[i];
    if (s >= N_NODES || d >= N_NODES) return;
    const float4* gs = g + (size_t)s * 4;
    float4* ad = acc + (size_t)d * 4;
    float4 v0 = gs[0], v1 = gs[1], v2 = gs[2], v3 = gs[3];
    atomicAdd(&ad[0], v0);
    atomicAdd(&ad[1], v1);
    atomicAdd(&ad[2], v2);
    atomicAdd(&ad[3], v3);
}

// ---------------- 4) mid: hr = relu(dinv*acc1+b1); g2 = dinv*hr; acc2 = g2 ---
__global__ void k_mid(const float* __restrict__ b1) {
    int i = blockIdx.x * blockDim.x + threadIdx.x;
    if (i >= N_NODES) return;
    float dv = d_dinv[i];
    const float4* bv = (const float4*)b1;
#pragma unroll
    for (int j = 0; j < 4; j++) {
        float4 a = d_acc1[i * 4 + j];
        float4 b = __ldg(&bv[j]);
        float4 h;
        h.x = fmaxf(fmaf(dv, a.x, b.x), 0.f);
        h.y = fmaxf(fmaf(dv, a.y, b.y), 0.f);
        h.z = fmaxf(fmaf(dv, a.z, b.z), 0.f);
        h.w = fmaxf(fmaf(dv, a.w, b.w), 0.f);
        float4 gq = f4scale(dv, h);
        d_g2[i * 4 + j] = gq;
        d_acc2[i * 4 + j] = gq;
    }
}

// ---------------- 5) final: out = (dinv*acc2) @ W2 + b2 ----------------------
__global__ void __launch_bounds__(256) k_final(const float* __restrict__ W2,
                                               const float* __restrict__ b2,
                                               float* __restrict__ out) {
    __shared__ float4 W2s[HIDDEN * 10];            // 16 x 40 floats = 160 f4
    const float4* wv = (const float4*)W2;
    if (threadIdx.x < HIDDEN * 10) W2s[threadIdx.x] = wv[threadIdx.x];
    __syncthreads();

    int r = blockIdx.x * 256 + threadIdx.x;
    if (r >= N_NODES) return;
    float dv = d_dinv[r];
    float a[HIDDEN];
#pragma unroll
    for (int j = 0; j < 4; j++) {
        float4 t = f4scale(dv, d_acc2[r * 4 + j]);
        a[j * 4 + 0] = t.x; a[j * 4 + 1] = t.y;
        a[j * 4 + 2] = t.z; a[j * 4 + 3] = t.w;
    }
    float4 o[10];
    const float4* bv = (const float4*)b2;
#pragma unroll
    for (int c = 0; c < 10; c++) o[c] = __ldg(&bv[c]);
#pragma unroll
    for (int k = 0; k < HIDDEN; k++) {
#pragma unroll
        for (int c = 0; c < 10; c++) o[c] = f4fma(a[k], W2s[k * 10 + c], o[c]);
    }
    float4* orow = (float4*)(out + (size_t)r * N_CLS);
#pragma unroll
    for (int c = 0; c < 10; c++) orow[c] = o[c];
}

// ---------------- launch ------------------------------------------------------
extern "C" void kernel_launch(void* const* d_in, const int* in_sizes, int n_in,
                              void* d_out, int out_size) {
    // Identify inputs by unique element counts (robust to ordering).
    const float* x  = nullptr;  const void* ei = nullptr;
    const float* W1 = nullptr;  const float* b1 = nullptr;
    const float* W2 = nullptr;  const float* b2 = nullptr;
    for (int i = 0; i < n_in; i++) {
        long long sz = in_sizes[i];
        if      (sz == (long long)N_NODES * D_FEAT) x  = (const float*)d_in[i];
        else if (sz == 2LL * N_EDGES)               ei = d_in[i];
        else if (sz == (long long)D_FEAT * HIDDEN)  W1 = (const float*)d_in[i];
        else if (sz == HIDDEN)                      b1 = (const float*)d_in[i];
        else if (sz == (long long)HIDDEN * N_CLS)   W2 = (const float*)d_in[i];
        else if (sz == N_CLS)                       b2 = (const float*)d_in[i];
    }
    float* out = (float*)d_out;

    float4* g1p;  cudaGetSymbolAddress((void**)&g1p,  d_g1);
    float4* a1p;  cudaGetSymbolAddress((void**)&a1p,  d_acc1);
    float4* g2p;  cudaGetSymbolAddress((void**)&g2p,  d_g2);
    float4* a2p;  cudaGetSymbolAddress((void**)&a2p,  d_acc2);

    const int TB = 256;
    int nb_n = (N_NODES + TB - 1) / TB;
    int nb_e = (N_EDGES + TB - 1) / TB;

    k_detect<<<1, 32>>>(ei);
    k_init_deg<<<nb_n, TB>>>();
    k_decode<<<nb_e, TB>>>(ei);
    k_dinv<<<nb_n, TB>>>();
    k_gemm1<<<nb_n, TB>>>(x, W1);
    k_scatter<<<nb_e, TB>>>(g1p, a1p);
    k_mid<<<nb_n, TB>>>(b1);
    k_scatter<<<nb_e, TB>>>(g2p, a2p);
    k_final<<<nb_n, TB>>>(W2, b2, out);
}

// round 4
// speedup vs baseline: 1.2213x; 1.2213x over previous
#include <cuda_runtime.h>
#include <cuda_bf16.h>

#define N_NODES 100000
#define N_EDGES 3200000
#define D_FEAT  512
#define HIDDEN  16
#define N_CLS   40
#define SCAN_BLK 1024
#define N_SCAN_BLKS ((N_NODES + SCAN_BLK - 1) / SCAN_BLK)   // 98

// ---------------- scratch (static device globals; no allocation) -------------
__device__ int    d_is64;
__device__ int    d_src [N_EDGES];
__device__ int    d_dst [N_EDGES];
__device__ int    d_csr_src[N_EDGES];          // src ids grouped by dst
__device__ int    d_deg [N_NODES];             // incoming edge count (no self)
__device__ int    d_ptr [N_NODES];             // exclusive prefix of deg
__device__ int    d_fill[N_NODES];
__device__ int    d_bsum[N_SCAN_BLKS];
__device__ float  d_dinv[N_NODES];
__device__ float4 d_g1  [N_NODES * 4];         // dinv[v] * (x[v] @ W1)
__device__ float4 d_g2  [N_NODES * 4];         // dinv[v] * relu(...)

__device__ __forceinline__ float4 f4fma(float a, float4 b, float4 c) {
    c.x = fmaf(a, b.x, c.x); c.y = fmaf(a, b.y, c.y);
    c.z = fmaf(a, b.z, c.z); c.w = fmaf(a, b.w, c.w);
    return c;
}
__device__ __forceinline__ float4 f4scale(float a, float4 b) {
    return make_float4(a * b.x, a * b.y, a * b.z, a * b.w);
}
__device__ __forceinline__ float4 f4add(float4 a, float4 b) {
    return make_float4(a.x + b.x, a.y + b.y, a.z + b.z, a.w + b.w);
}

// ---------------- 0) edge dtype detect ---------------------------------------
__global__ void k_detect(const void* __restrict__ ei) {
    if (threadIdx.x == 0 && blockIdx.x == 0) {
        const unsigned long long* p = (const unsigned long long*)ei;
        int is64 = 1;
        for (int i = 0; i < 64; i++)
            if (p[i] >= (unsigned long long)N_NODES) { is64 = 0; break; }
        d_is64 = is64;
    }
}

// ---------------- 1a) zero counters ------------------------------------------
__global__ void k_init() {
    int i = blockIdx.x * blockDim.x + threadIdx.x;
    if (i < N_NODES) { d_deg[i] = 0; d_fill[i] = 0; }
}

// ---------------- 1b) decode edges + count degrees ---------------------------
__global__ void __launch_bounds__(256) k_decode(const void* __restrict__ ei) {
    int i = blockIdx.x * blockDim.x + threadIdx.x;
    if (i >= N_EDGES) return;
    int s, d;
    if (d_is64) {
        const long long* p = (const long long*)ei;
        s = (int)p[i];
        d = (int)p[i + N_EDGES];
    } else {
        const int* p = (const int*)ei;
        s = p[i];
        d = p[i + N_EDGES];
    }
    d_src[i] = s;
    d_dst[i] = d;
    if ((unsigned)d < N_NODES) atomicAdd(&d_deg[d], 1);
}

// ---------------- 1c) dinv ----------------------------------------------------
__global__ void k_dinv() {
    int i = blockIdx.x * blockDim.x + threadIdx.x;
    if (i < N_NODES) d_dinv[i] = rsqrtf((float)(d_deg[i] + 1));
}

// ---------------- 2) prefix scan of deg -> ptr --------------------------------
__global__ void __launch_bounds__(SCAN_BLK) k_scan1() {
    __shared__ int sm[SCAN_BLK];
    int t = threadIdx.x;
    int i = blockIdx.x * SCAN_BLK + t;
    int val = (i < N_NODES) ? d_deg[i] : 0;
    sm[t] = val;
    __syncthreads();
#pragma unroll
    for (int off = 1; off < SCAN_BLK; off <<= 1) {
        int x = (t >= off) ? sm[t - off] : 0;
        __syncthreads();
        sm[t] += x;
        __syncthreads();
    }
    if (i < N_NODES) d_ptr[i] = sm[t] - val;        // exclusive, pre-offset
    if (t == SCAN_BLK - 1) d_bsum[blockIdx.x] = sm[t];
}
__global__ void k_scan2() {
    if (threadIdx.x == 0 && blockIdx.x == 0) {
        int run = 0;
        for (int b = 0; b < N_SCAN_BLKS; b++) {
            int t = d_bsum[b];
            d_bsum[b] = run;
            run += t;
        }
    }
}
__global__ void k_scan3() {
    int i = blockIdx.x * blockDim.x + threadIdx.x;
    if (i < N_NODES) d_ptr[i] += d_bsum[i / SCAN_BLK];
}

// ---------------- 3) bucket fill: csr_src grouped by dst ----------------------
__global__ void __launch_bounds__(256) k_fill() {
    int i = blockIdx.x * blockDim.x + threadIdx.x;
    if (i >= N_EDGES) return;
    unsigned s = (unsigned)d_src[i];
    unsigned d = (unsigned)d_dst[i];
    if (s >= N_NODES || d >= N_NODES) return;
    int pos = d_ptr[d] + atomicAdd(&d_fill[d], 1);
    d_csr_src[pos] = (int)s;
}

// ---------------- 4) GEMM1: g1 = dinv * (x @ W1) ------------------------------
__global__ void __launch_bounds__(256) k_gemm1(const float* __restrict__ x,
                                               const float* __restrict__ W1) {
    __shared__ float4 Ws[D_FEAT * 4];              // [k][c4], 32 KB
    const float4* wv = (const float4*)W1;
    for (int i = threadIdx.x; i < D_FEAT * 4; i += 256) Ws[i] = wv[i];
    __syncthreads();

    int r = blockIdx.x * 256 + threadIdx.x;
    if (r >= N_NODES) return;

    float4 acc0 = make_float4(0.f, 0.f, 0.f, 0.f);
    float4 acc1 = acc0, acc2 = acc0, acc3 = acc0;
    const float4* xr = (const float4*)(x + (size_t)r * D_FEAT);

#pragma unroll 4
    for (int k4 = 0; k4 < D_FEAT / 4; k4++) {
        float4 xv = xr[k4];
        const float4* w = &Ws[(k4 * 4) * 4];
#pragma unroll
        for (int m = 0; m < 4; m++) {
            float xk = (m == 0) ? xv.x : (m == 1) ? xv.y : (m == 2) ? xv.z : xv.w;
            acc0 = f4fma(xk, w[m * 4 + 0], acc0);
            acc1 = f4fma(xk, w[m * 4 + 1], acc1);
            acc2 = f4fma(xk, w[m * 4 + 2], acc2);
            acc3 = f4fma(xk, w[m * 4 + 3], acc3);
        }
    }
    float dv = d_dinv[r];
    d_g1[r * 4 + 0] = f4scale(dv, acc0);
    d_g1[r * 4 + 1] = f4scale(dv, acc1);
    d_g1[r * 4 + 2] = f4scale(dv, acc2);
    d_g1[r * 4 + 3] = f4scale(dv, acc3);
}

// ---------------- warp-gather reduction helper --------------------------------
// warp handles node v; 4 lanes per edge (q = lane&3 selects float4 quarter).
// Returns per-lane float4 holding the full incoming sum for quarter q.
__device__ __forceinline__ float4 warp_aggregate(int v, int lane,
                                                 const float4* __restrict__ g) {
    int q   = lane & 3;
    int sub = lane >> 2;
    int beg = d_ptr[v];
    int end = beg + d_deg[v];
    float4 acc = make_float4(0.f, 0.f, 0.f, 0.f);
    for (int e = beg + sub; e < end; e += 8) {
        int s = d_csr_src[e];
        acc = f4add(acc, __ldg(&g[(size_t)s * 4 + q]));
    }
#pragma unroll
    for (int off = 16; off >= 4; off >>= 1) {
        acc.x += __shfl_xor_sync(0xffffffff, acc.x, off);
        acc.y += __shfl_xor_sync(0xffffffff, acc.y, off);
        acc.z += __shfl_xor_sync(0xffffffff, acc.z, off);
        acc.w += __shfl_xor_sync(0xffffffff, acc.w, off);
    }
    return acc;   // valid on all lanes (per quarter q)
}

// ---------------- 5) aggr1 + mid: g2 = dinv * relu(dinv*(sum+self) + b1) ------
__global__ void __launch_bounds__(256) k_aggr1(const float* __restrict__ b1) {
    int v = blockIdx.x * 8 + (threadIdx.x >> 5);
    if (v >= N_NODES) return;
    int lane = threadIdx.x & 31;
    int q = lane & 3;

    float4 acc = warp_aggregate(v, lane, d_g1);
    if ((lane >> 2) == 0) {
        float dv = d_dinv[v];
        float4 a = f4add(acc, d_g1[(size_t)v * 4 + q]);   // + self loop
        float4 b = __ldg(&((const float4*)b1)[q]);
        float4 h;
        h.x = fmaxf(fmaf(dv, a.x, b.x), 0.f);
        h.y = fmaxf(fmaf(dv, a.y, b.y), 0.f);
        h.z = fmaxf(fmaf(dv, a.z, b.z), 0.f);
        h.w = fmaxf(fmaf(dv, a.w, b.w), 0.f);
        d_g2[(size_t)v * 4 + q] = f4scale(dv, h);
    }
}

// ---------------- 6) aggr2 + final: out = (dinv*(sum+self)) @ W2 + b2 ---------
__global__ void __launch_bounds__(256) k_aggr2(const float* __restrict__ W2,
                                               const float* __restrict__ b2,
                                               float* __restrict__ out) {
    __shared__ float W2s[HIDDEN * N_CLS];
    __shared__ float b2s[N_CLS];
    for (int i = threadIdx.x; i < HIDDEN * N_CLS; i += 256) W2s[i] = W2[i];
    if (threadIdx.x < N_CLS) b2s[threadIdx.x] = b2[threadIdx.x];
    __syncthreads();

    int v = blockIdx.x * 8 + (threadIdx.x >> 5);
    if (v >= N_NODES) return;
    int lane = threadIdx.x & 31;
    int q = lane & 3;

    float4 acc = warp_aggregate(v, lane, d_g2);
    float dv = d_dinv[v];
    float4 a4 = f4scale(dv, f4add(acc, d_g2[(size_t)v * 4 + q]));
    float comp[4] = {a4.x, a4.y, a4.z, a4.w};

    int c1 = 32 + (lane & 7);
    float o0 = b2s[lane];
    float o1 = b2s[c1];
#pragma unroll
    for (int k = 0; k < HIDDEN; k++) {
        float ak = __shfl_sync(0xffffffff, comp[k & 3], k >> 2);
        o0 = fmaf(ak, W2s[k * N_CLS + lane], o0);
        o1 = fmaf(ak, W2s[k * N_CLS + c1], o1);
    }
    out[(size_t)v * N_CLS + lane] = o0;
    if (lane < 8) out[(size_t)v * N_CLS + c1] = o1;
}

// ---------------- launch ------------------------------------------------------
extern "C" void kernel_launch(void* const* d_in, const int* in_sizes, int n_in,
                              void* d_out, int out_size) {
    const float* x  = nullptr;  const void* ei = nullptr;
    const float* W1 = nullptr;  const float* b1 = nullptr;
    const float* W2 = nullptr;  const float* b2 = nullptr;
    for (int i = 0; i < n_in; i++) {
        long long sz = in_sizes[i];
        if      (sz == (long long)N_NODES * D_FEAT) x  = (const float*)d_in[i];
        else if (sz == 2LL * N_EDGES)               ei = d_in[i];
        else if (sz == (long long)D_FEAT * HIDDEN)  W1 = (const float*)d_in[i];
        else if (sz == HIDDEN)                      b1 = (const float*)d_in[i];
        else if (sz == (long long)HIDDEN * N_CLS)   W2 = (const float*)d_in[i];
        else if (sz == N_CLS)                       b2 = (const float*)d_in[i];
    }
    float* out = (float*)d_out;

    const int TB = 256;
    int nb_n = (N_NODES + TB - 1) / TB;
    int nb_e = (N_EDGES + TB - 1) / TB;
    int nb_w = (N_NODES + 7) / 8;          // warp-per-node kernels

    k_detect<<<1, 32>>>(ei);
    k_init<<<nb_n, TB>>>();
    k_decode<<<nb_e, TB>>>(ei);
    k_dinv<<<nb_n, TB>>>();
    k_scan1<<<N_SCAN_BLKS, SCAN_BLK>>>();
    k_scan2<<<1, 32>>>();
    k_scan3<<<nb_n, TB>>>();
    k_fill<<<nb_e, TB>>>();
    k_gemm1<<<nb_n, TB>>>(x, W1);
    k_aggr1<<<nb_w, TB>>>(b1);
    k_aggr2<<<nb_w, TB>>>(W2, b2, out);
}